// round 16
// baseline (speedup 1.0000x reference)
#include <cuda_runtime.h>
#include <math.h>

#define MAX_NODES 101001
#define EMBED     64
#define MAX_EDGES 2020020
#define EPS_F     1e-12f
#define FULL      0xffffffffu

// Scratch (allocation-free: __device__ globals)
__device__ float g_ew[MAX_EDGES];        // exp(logit)  (unnormalized weights)
__device__ float g_rs[MAX_NODES];        // 1 / max(rowsum, EPS)
__device__ int   g_rowptr[MAX_NODES + 1];

// ---------------------------------------------------------------------------
// K1: CSR row pointers via boundary scan, int4-vectorized (4 edges/thread).
// ---------------------------------------------------------------------------
__global__ void k_rowptr(const int* __restrict__ erow, int n, int e) {
    int qi   = blockIdx.x * blockDim.x + threadIdx.x;
    int base = qi * 4;
    if (base >= e) return;

    int vals[5];
    vals[0] = (base == 0) ? -1 : erow[base - 1];
    if (base + 4 <= e) {
        int4 v = *(const int4*)(erow + base);
        vals[1] = v.x; vals[2] = v.y; vals[3] = v.z; vals[4] = v.w;
    } else {
        int m = e - base;
        for (int k = 0; k < 4; ++k)
            vals[k + 1] = (k < m) ? erow[base + k] : vals[k];
    }
    #pragma unroll
    for (int k = 0; k < 4; ++k) {
        if (base + k >= e) break;
        for (int v = vals[k] + 1; v <= vals[k + 1]; ++v) g_rowptr[v] = base + k;
    }
    if (base + 4 >= e) {
        for (int v = vals[4] + 1; v <= n; ++v) g_rowptr[v] = e;
    }
}

// ---------------------------------------------------------------------------
// K2 (FUSED): softmax + layer-1 propagation in ONE edge pass (warp per row),
// 4 edges/iter, __expf. ew writes staged in shared per 32-edge batch and
// flushed with ONE coalesced STG (replaces ~10 scattered STG.32 per row).
// Also emits the layer-0 h0 copy.
// ---------------------------------------------------------------------------
__global__ void __launch_bounds__(256)
k_prop1_fused(const float* __restrict__ h0,
              const float* __restrict__ h_att,
              const float* __restrict__ t_att,
              const int*   __restrict__ ecol,
              const float* __restrict__ W,      // [64,64] row-major
              const float* __restrict__ b,
              float*       __restrict__ out0,   // layer-0 slice (h0 copy)
              float*       __restrict__ out, int n) {
    __shared__ float a_sh[8][80];   // row k stored at (k>>4)*20 + (k&15)
    __shared__ float o_sh[8][66];   // post-ReLU activations per row
    __shared__ float ew_sh[8][32];  // per-warp ew staging buffer

    int wwarp = threadIdx.x >> 5;
    int lane  = threadIdx.x & 31;
    int rowbase = blockIdx.x * 8;
    int row   = rowbase + wwarp;
    bool rvalid = row < n;

    int half = lane >> 4;
    int hl   = lane & 15;

    int beg = 0, end = 0;
    if (rvalid) { beg = g_rowptr[row]; end = g_rowptr[row + 1]; }

    float4 ha = make_float4(0.f, 0.f, 0.f, 0.f);
    if (rvalid) ha = ((const float4*)(h_att + (size_t)row * EMBED))[hl];

    float  s    = 0.f;                               // per-half row sum
    float4 acc0 = make_float4(0.f, 0.f, 0.f, 0.f);
    float4 acc1 = make_float4(0.f, 0.f, 0.f, 0.f);
    for (int base = beg; base < end; base += 32) {
        int idx = base + lane;
        int c   = (idx < end) ? ecol[idx] : 0;      // coalesced batch
        int cnt = min(32, end - base);
        int j = 0;
        for (; j + 4 <= cnt; j += 4) {
            int cc0 = __shfl_sync(FULL, c, j + half);
            int cc1 = __shfl_sync(FULL, c, j + 2 + half);
            float4 tv0 = ((const float4*)(t_att + (size_t)cc0 * EMBED))[hl];
            float4 hv0 = ((const float4*)(h0    + (size_t)cc0 * EMBED))[hl];
            float4 tv1 = ((const float4*)(t_att + (size_t)cc1 * EMBED))[hl];
            float4 hv1 = ((const float4*)(h0    + (size_t)cc1 * EMBED))[hl];
            float p0 = ha.x*tv0.x + ha.y*tv0.y + ha.z*tv0.z + ha.w*tv0.w;
            float p1 = ha.x*tv1.x + ha.y*tv1.y + ha.z*tv1.z + ha.w*tv1.w;
            #pragma unroll
            for (int o = 8; o; o >>= 1) {
                p0 += __shfl_xor_sync(FULL, p0, o);
                p1 += __shfl_xor_sync(FULL, p1, o);
            }
            float e0 = __expf(p0);                   // uniform within half
            float e1 = __expf(p1);
            if (hl == 0) {
                ew_sh[wwarp][j + half]     = e0;     // STS, conflict-free
                ew_sh[wwarp][j + 2 + half] = e1;
            }
            s += e0 + e1;
            acc0.x = fmaf(e0, hv0.x, acc0.x); acc0.y = fmaf(e0, hv0.y, acc0.y);
            acc0.z = fmaf(e0, hv0.z, acc0.z); acc0.w = fmaf(e0, hv0.w, acc0.w);
            acc1.x = fmaf(e1, hv1.x, acc1.x); acc1.y = fmaf(e1, hv1.y, acc1.y);
            acc1.z = fmaf(e1, hv1.z, acc1.z); acc1.w = fmaf(e1, hv1.w, acc1.w);
        }
        for (; j < cnt; j += 2) {
            int  jj = j + half; if (jj >= cnt) jj = cnt - 1;   // clamp odd tail
            int  cc = __shfl_sync(FULL, c, jj);
            float4 tv = ((const float4*)(t_att + (size_t)cc * EMBED))[hl];
            float4 hv = ((const float4*)(h0    + (size_t)cc * EMBED))[hl];
            float p = ha.x*tv.x + ha.y*tv.y + ha.z*tv.z + ha.w*tv.w;
            #pragma unroll
            for (int o = 8; o; o >>= 1) p += __shfl_xor_sync(FULL, p, o);
            float e = __expf(p);
            bool valid = (half == 0) || (j + 1 < cnt);
            float we = valid ? e : 0.f;
            s += we;
            if (valid && hl == 0) ew_sh[wwarp][j + half] = e;
            acc0.x = fmaf(we, hv.x, acc0.x); acc0.y = fmaf(we, hv.y, acc0.y);
            acc0.z = fmaf(we, hv.z, acc0.z); acc0.w = fmaf(we, hv.w, acc0.w);
        }
        __syncwarp();
        if (lane < cnt) g_ew[idx] = ew_sh[wwarp][lane];   // ONE coalesced STG
        __syncwarp();
    }
    float4 acc = make_float4(acc0.x + acc1.x, acc0.y + acc1.y,
                             acc0.z + acc1.z, acc0.w + acc1.w);
    // combine half-warp partials
    float s_tot = s + __shfl_xor_sync(FULL, s, 16);
    acc.x += __shfl_xor_sync(FULL, acc.x, 16);
    acc.y += __shfl_xor_sync(FULL, acc.y, 16);
    acc.z += __shfl_xor_sync(FULL, acc.z, 16);
    acc.w += __shfl_xor_sync(FULL, acc.w, 16);

    float rs = __fdividef(1.f, fmaxf(s_tot, EPS_F));
    if (rvalid && lane == 0) g_rs[row] = rs;        // for layer 2
    if (beg == end) rs = 0.f;

    float4 hr = make_float4(0.f, 0.f, 0.f, 0.f);
    if (rvalid) hr = ((const float4*)(h0 + (size_t)row * EMBED))[hl];
    acc.x = fmaf(rs, acc.x, hr.x);
    acc.y = fmaf(rs, acc.y, hr.y);
    acc.z = fmaf(rs, acc.z, hr.z);
    acc.w = fmaf(rs, acc.w, hr.w);

    if (half == 0) {
        // layer-0 output = h0 (replaces the host memcpy)
        if (rvalid) ((float4*)(out0 + (size_t)row * EMBED))[hl] = hr;
        float* dst = a_sh[wwarp] + (hl >> 2) * 20 + (hl & 3) * 4;
        *(float4*)dst = acc;
    }

    // ---- W slice into registers: thread (jj, q) holds W[j][16q..16q+15] ----
    int jj = lane >> 2;
    int q  = lane & 3;
    int j  = wwarp * 8 + jj;
    const float4* wrow = (const float4*)(W + j * EMBED + q * 16);
    float4 w0 = wrow[0], w1 = wrow[1], w2 = wrow[2], w3 = wrow[3];
    float  bj = b[j];

    __syncthreads();

    #pragma unroll
    for (int r = 0; r < 8; ++r) {
        const float* aq = a_sh[r] + q * 20;
        float4 a0 = ((const float4*)aq)[0];
        float4 a1 = ((const float4*)aq)[1];
        float4 a2 = ((const float4*)aq)[2];
        float4 a3 = ((const float4*)aq)[3];
        float p = a0.x*w0.x + a0.y*w0.y + a0.z*w0.z + a0.w*w0.w;
        p = fmaf(a1.x, w1.x, p); p = fmaf(a1.y, w1.y, p);
        p = fmaf(a1.z, w1.z, p); p = fmaf(a1.w, w1.w, p);
        p = fmaf(a2.x, w2.x, p); p = fmaf(a2.y, w2.y, p);
        p = fmaf(a2.z, w2.z, p); p = fmaf(a2.w, w2.w, p);
        p = fmaf(a3.x, w3.x, p); p = fmaf(a3.y, w3.y, p);
        p = fmaf(a3.z, w3.z, p); p = fmaf(a3.w, w3.w, p);
        p += __shfl_xor_sync(FULL, p, 1);
        p += __shfl_xor_sync(FULL, p, 2);
        if (q == 0) o_sh[r][j] = fmaxf(p + bj, 0.f);
    }
    __syncthreads();

    if (rvalid) {
        float o1 = o_sh[wwarp][lane];
        float o2 = o_sh[wwarp][lane + 32];
        float sq = o1 * o1 + o2 * o2;
        #pragma unroll
        for (int o = 16; o; o >>= 1) sq += __shfl_xor_sync(FULL, sq, o);
        float inv = rsqrtf(fmaxf(sq, EPS_F * EPS_F));
        float* orow = out + (size_t)row * EMBED;
        orow[lane]      = o1 * inv;
        orow[lane + 32] = o2 * inv;
    }
}

// ---------------------------------------------------------------------------
// K3: layer-2 propagation (reads g_ew / g_rs), gather unrolled x4
// (8 edges/iter, 8 independent LDG.128s in flight). [R11 champion structure]
// ---------------------------------------------------------------------------
__global__ void __launch_bounds__(256)
k_prop(const float* __restrict__ h_prev,
       const int*   __restrict__ ecol,
       const float* __restrict__ W,      // [64,64] row-major
       const float* __restrict__ b,
       float*       __restrict__ out, int n) {
    __shared__ float a_sh[8][80];
    __shared__ float o_sh[8][66];

    int wwarp = threadIdx.x >> 5;
    int lane  = threadIdx.x & 31;
    int rowbase = blockIdx.x * 8;
    int row   = rowbase + wwarp;
    bool rvalid = row < n;

    int half = lane >> 4;
    int hl   = lane & 15;

    int beg = 0, end = 0;
    if (rvalid) { beg = g_rowptr[row]; end = g_rowptr[row + 1]; }

    float4 acc0 = make_float4(0.f, 0.f, 0.f, 0.f);
    float4 acc1 = make_float4(0.f, 0.f, 0.f, 0.f);
    for (int base = beg; base < end; base += 32) {
        int   idx = base + lane;
        bool  v   = idx < end;
        int   c   = v ? ecol[idx] : 0;
        float w   = v ? g_ew[idx] : 0.f;
        int   cnt = min(32, end - base);
        int j = 0;
        for (; j + 8 <= cnt; j += 8) {
            int   cc0 = __shfl_sync(FULL, c, j + half);
            int   cc1 = __shfl_sync(FULL, c, j + 2 + half);
            int   cc2 = __shfl_sync(FULL, c, j + 4 + half);
            int   cc3 = __shfl_sync(FULL, c, j + 6 + half);
            float ws0 = __shfl_sync(FULL, w, j + half);
            float ws1 = __shfl_sync(FULL, w, j + 2 + half);
            float ws2 = __shfl_sync(FULL, w, j + 4 + half);
            float ws3 = __shfl_sync(FULL, w, j + 6 + half);
            float4 hv0 = ((const float4*)(h_prev + (size_t)cc0 * EMBED))[hl];
            float4 hv1 = ((const float4*)(h_prev + (size_t)cc1 * EMBED))[hl];
            float4 hv2 = ((const float4*)(h_prev + (size_t)cc2 * EMBED))[hl];
            float4 hv3 = ((const float4*)(h_prev + (size_t)cc3 * EMBED))[hl];
            acc0.x = fmaf(ws0, hv0.x, acc0.x); acc0.y = fmaf(ws0, hv0.y, acc0.y);
            acc0.z = fmaf(ws0, hv0.z, acc0.z); acc0.w = fmaf(ws0, hv0.w, acc0.w);
            acc1.x = fmaf(ws1, hv1.x, acc1.x); acc1.y = fmaf(ws1, hv1.y, acc1.y);
            acc1.z = fmaf(ws1, hv1.z, acc1.z); acc1.w = fmaf(ws1, hv1.w, acc1.w);
            acc0.x = fmaf(ws2, hv2.x, acc0.x); acc0.y = fmaf(ws2, hv2.y, acc0.y);
            acc0.z = fmaf(ws2, hv2.z, acc0.z); acc0.w = fmaf(ws2, hv2.w, acc0.w);
            acc1.x = fmaf(ws3, hv3.x, acc1.x); acc1.y = fmaf(ws3, hv3.y, acc1.y);
            acc1.z = fmaf(ws3, hv3.z, acc1.z); acc1.w = fmaf(ws3, hv3.w, acc1.w);
        }
        for (; j < cnt; j += 2) {
            int   jj = j + half; if (jj >= cnt) jj = cnt - 1;
            int   cc = __shfl_sync(FULL, c, jj);
            float ws = __shfl_sync(FULL, w, jj);
            if (half && (j + 1 >= cnt)) ws = 0.f;
            float4 hv = ((const float4*)(h_prev + (size_t)cc * EMBED))[hl];
            acc0.x = fmaf(ws, hv.x, acc0.x); acc0.y = fmaf(ws, hv.y, acc0.y);
            acc0.z = fmaf(ws, hv.z, acc0.z); acc0.w = fmaf(ws, hv.w, acc0.w);
        }
    }
    float4 acc = make_float4(acc0.x + acc1.x, acc0.y + acc1.y,
                             acc0.z + acc1.z, acc0.w + acc1.w);
    acc.x += __shfl_xor_sync(FULL, acc.x, 16);
    acc.y += __shfl_xor_sync(FULL, acc.y, 16);
    acc.z += __shfl_xor_sync(FULL, acc.z, 16);
    acc.w += __shfl_xor_sync(FULL, acc.w, 16);

    float rs = (beg < end) ? g_rs[row] : 0.f;
    float4 hr = make_float4(0.f, 0.f, 0.f, 0.f);
    if (rvalid) hr = ((const float4*)(h_prev + (size_t)row * EMBED))[hl];
    acc.x = fmaf(rs, acc.x, hr.x);
    acc.y = fmaf(rs, acc.y, hr.y);
    acc.z = fmaf(rs, acc.z, hr.z);
    acc.w = fmaf(rs, acc.w, hr.w);

    if (half == 0) {
        float* dst = a_sh[wwarp] + (hl >> 2) * 20 + (hl & 3) * 4;
        *(float4*)dst = acc;
    }

    int jj = lane >> 2;
    int q  = lane & 3;
    int j  = wwarp * 8 + jj;
    const float4* wrow = (const float4*)(W + j * EMBED + q * 16);
    float4 w0 = wrow[0], w1 = wrow[1], w2 = wrow[2], w3 = wrow[3];
    float  bj = b[j];

    __syncthreads();

    #pragma unroll
    for (int r = 0; r < 8; ++r) {
        const float* aq = a_sh[r] + q * 20;
        float4 a0 = ((const float4*)aq)[0];
        float4 a1 = ((const float4*)aq)[1];
        float4 a2 = ((const float4*)aq)[2];
        float4 a3 = ((const float4*)aq)[3];
        float p = a0.x*w0.x + a0.y*w0.y + a0.z*w0.z + a0.w*w0.w;
        p = fmaf(a1.x, w1.x, p); p = fmaf(a1.y, w1.y, p);
        p = fmaf(a1.z, w1.z, p); p = fmaf(a1.w, w1.w, p);
        p = fmaf(a2.x, w2.x, p); p = fmaf(a2.y, w2.y, p);
        p = fmaf(a2.z, w2.z, p); p = fmaf(a2.w, w2.w, p);
        p = fmaf(a3.x, w3.x, p); p = fmaf(a3.y, w3.y, p);
        p = fmaf(a3.z, w3.z, p); p = fmaf(a3.w, w3.w, p);
        p += __shfl_xor_sync(FULL, p, 1);
        p += __shfl_xor_sync(FULL, p, 2);
        if (q == 0) o_sh[r][j] = fmaxf(p + bj, 0.f);
    }
    __syncthreads();

    if (rvalid) {
        float o1 = o_sh[wwarp][lane];
        float o2 = o_sh[wwarp][lane + 32];
        float sq = o1 * o1 + o2 * o2;
        #pragma unroll
        for (int o = 16; o; o >>= 1) sq += __shfl_xor_sync(FULL, sq, o);
        float inv = rsqrtf(fmaxf(sq, EPS_F * EPS_F));
        float* orow = out + (size_t)row * EMBED;
        orow[lane]      = o1 * inv;
        orow[lane + 32] = o2 * inv;
    }
}

// ---------------------------------------------------------------------------
extern "C" void kernel_launch(void* const* d_in, const int* in_sizes, int n_in,
                              void* d_out, int out_size) {
    const float* h0    = (const float*)d_in[0];
    const float* h_att = (const float*)d_in[1];
    const float* t_att = (const float*)d_in[2];
    const float* w1    = (const float*)d_in[3];
    const float* b1    = (const float*)d_in[4];
    const float* w2    = (const float*)d_in[5];
    const float* b2    = (const float*)d_in[6];
    const int*   erow  = (const int*)d_in[7];
    const int*   ecol  = (const int*)d_in[8];
    float* out = (float*)d_out;

    int n = in_sizes[0] / EMBED;
    int e = in_sizes[8];
    if (n > MAX_NODES) n = MAX_NODES;
    if (e > MAX_EDGES) e = MAX_EDGES;

    {   // row pointers: int4 boundary scan over sorted erow
        int threads = 256;
        int quads   = (e + 3) / 4;
        int blocks  = (quads + threads - 1) / threads;
        k_rowptr<<<blocks, threads>>>(erow, n, e);
    }
    {
        int blocks = (n + 7) / 8;          // 8 rows per block, warp per row
        float* l1 = out + (size_t)n * EMBED;
        float* l2 = out + (size_t)2 * n * EMBED;
        // layer 1: fused softmax + propagation; also emits layer-0 copy
        k_prop1_fused<<<blocks, 256>>>(h0, h_att, t_att, ecol, w1, b1, out, l1, n);
        // layer 2: standard propagation using cached weights
        k_prop<<<blocks, 256>>>(l1, ecol, w2, b2, l2, n);
    }
}

// round 17
// speedup vs baseline: 1.0235x; 1.0235x over previous
#include <cuda_runtime.h>
#include <math.h>

#define MAX_NODES 101001
#define EMBED     64
#define MAX_EDGES 2020020
#define EPS_F     1e-12f
#define FULL      0xffffffffu

// Scratch (allocation-free: __device__ globals)
__device__ float g_ew[MAX_EDGES];        // exp(logit)  (unnormalized weights)
__device__ float g_rs[MAX_NODES];        // 1 / max(rowsum, EPS)
__device__ int   g_rowptr[MAX_NODES + 1];

// ---------------------------------------------------------------------------
// K1: CSR row pointers via boundary scan, int4-vectorized (4 edges/thread).
// ---------------------------------------------------------------------------
__global__ void k_rowptr(const int* __restrict__ erow, int n, int e) {
    int qi   = blockIdx.x * blockDim.x + threadIdx.x;
    int base = qi * 4;
    if (base >= e) return;

    int vals[5];
    vals[0] = (base == 0) ? -1 : erow[base - 1];
    if (base + 4 <= e) {
        int4 v = *(const int4*)(erow + base);
        vals[1] = v.x; vals[2] = v.y; vals[3] = v.z; vals[4] = v.w;
    } else {
        int m = e - base;
        for (int k = 0; k < 4; ++k)
            vals[k + 1] = (k < m) ? erow[base + k] : vals[k];
    }
    #pragma unroll
    for (int k = 0; k < 4; ++k) {
        if (base + k >= e) break;
        for (int v = vals[k] + 1; v <= vals[k + 1]; ++v) g_rowptr[v] = base + k;
    }
    if (base + 4 >= e) {
        for (int v = vals[4] + 1; v <= n; ++v) g_rowptr[v] = e;
    }
}

// ---------------------------------------------------------------------------
// K2 (FUSED): softmax + layer-1 propagation (warp per row), 16 ROWS PER BLOCK
// (each warp gathers 2 rows sequentially) to amortize the register-resident
// W-slice load across 2x the rows. Edge loop is the R15-champion x2 unroll
// with scattered predicated ew stores. Also emits the layer-0 h0 copy.
// ---------------------------------------------------------------------------
__global__ void __launch_bounds__(256)
k_prop1_fused(const float* __restrict__ h0,
              const float* __restrict__ h_att,
              const float* __restrict__ t_att,
              const int*   __restrict__ ecol,
              const float* __restrict__ W,      // [64,64] row-major
              const float* __restrict__ b,
              float*       __restrict__ out0,   // layer-0 slice (h0 copy)
              float*       __restrict__ out, int n) {
    __shared__ float a_sh[16][80];  // row k stored at (k>>4)*20 + (k&15)
    __shared__ float o_sh[16][66];  // post-ReLU activations per row

    int wwarp = threadIdx.x >> 5;
    int lane  = threadIdx.x & 31;
    int rowbase = blockIdx.x * 16;

    int half = lane >> 4;
    int hl   = lane & 15;

    #pragma unroll
    for (int rr = 0; rr < 2; ++rr) {
        int row = rowbase + wwarp + 8 * rr;
        bool rvalid = row < n;

        int beg = 0, end = 0;
        if (rvalid) { beg = g_rowptr[row]; end = g_rowptr[row + 1]; }

        float4 ha = make_float4(0.f, 0.f, 0.f, 0.f);
        if (rvalid) ha = ((const float4*)(h_att + (size_t)row * EMBED))[hl];

        float  s    = 0.f;                               // per-half row sum
        float4 acc0 = make_float4(0.f, 0.f, 0.f, 0.f);
        float4 acc1 = make_float4(0.f, 0.f, 0.f, 0.f);
        for (int base = beg; base < end; base += 32) {
            int idx = base + lane;
            int c   = (idx < end) ? ecol[idx] : 0;      // coalesced batch
            int cnt = min(32, end - base);
            int j = 0;
            for (; j + 4 <= cnt; j += 4) {
                int cc0 = __shfl_sync(FULL, c, j + half);
                int cc1 = __shfl_sync(FULL, c, j + 2 + half);
                float4 tv0 = ((const float4*)(t_att + (size_t)cc0 * EMBED))[hl];
                float4 hv0 = ((const float4*)(h0    + (size_t)cc0 * EMBED))[hl];
                float4 tv1 = ((const float4*)(t_att + (size_t)cc1 * EMBED))[hl];
                float4 hv1 = ((const float4*)(h0    + (size_t)cc1 * EMBED))[hl];
                float p0 = ha.x*tv0.x + ha.y*tv0.y + ha.z*tv0.z + ha.w*tv0.w;
                float p1 = ha.x*tv1.x + ha.y*tv1.y + ha.z*tv1.z + ha.w*tv1.w;
                #pragma unroll
                for (int o = 8; o; o >>= 1) {
                    p0 += __shfl_xor_sync(FULL, p0, o);
                    p1 += __shfl_xor_sync(FULL, p1, o);
                }
                float e0 = __expf(p0);                   // uniform within half
                float e1 = __expf(p1);
                if (hl == 0) {
                    g_ew[base + j + half]     = e0;
                    g_ew[base + j + 2 + half] = e1;
                }
                s += e0 + e1;
                acc0.x = fmaf(e0, hv0.x, acc0.x); acc0.y = fmaf(e0, hv0.y, acc0.y);
                acc0.z = fmaf(e0, hv0.z, acc0.z); acc0.w = fmaf(e0, hv0.w, acc0.w);
                acc1.x = fmaf(e1, hv1.x, acc1.x); acc1.y = fmaf(e1, hv1.y, acc1.y);
                acc1.z = fmaf(e1, hv1.z, acc1.z); acc1.w = fmaf(e1, hv1.w, acc1.w);
            }
            for (; j < cnt; j += 2) {
                int  jj = j + half; if (jj >= cnt) jj = cnt - 1;  // clamp tail
                int  cc = __shfl_sync(FULL, c, jj);
                float4 tv = ((const float4*)(t_att + (size_t)cc * EMBED))[hl];
                float4 hv = ((const float4*)(h0    + (size_t)cc * EMBED))[hl];
                float p = ha.x*tv.x + ha.y*tv.y + ha.z*tv.z + ha.w*tv.w;
                #pragma unroll
                for (int o = 8; o; o >>= 1) p += __shfl_xor_sync(FULL, p, o);
                float e = __expf(p);
                bool valid = (half == 0) || (j + 1 < cnt);
                float we = valid ? e : 0.f;
                s += we;
                if (valid && hl == 0) g_ew[base + j + half] = e;
                acc0.x = fmaf(we, hv.x, acc0.x); acc0.y = fmaf(we, hv.y, acc0.y);
                acc0.z = fmaf(we, hv.z, acc0.z); acc0.w = fmaf(we, hv.w, acc0.w);
            }
        }
        float4 acc = make_float4(acc0.x + acc1.x, acc0.y + acc1.y,
                                 acc0.z + acc1.z, acc0.w + acc1.w);
        float s_tot = s + __shfl_xor_sync(FULL, s, 16);
        acc.x += __shfl_xor_sync(FULL, acc.x, 16);
        acc.y += __shfl_xor_sync(FULL, acc.y, 16);
        acc.z += __shfl_xor_sync(FULL, acc.z, 16);
        acc.w += __shfl_xor_sync(FULL, acc.w, 16);

        float rs = __fdividef(1.f, fmaxf(s_tot, EPS_F));
        if (rvalid && lane == 0) g_rs[row] = rs;        // for layer 2
        if (beg == end) rs = 0.f;

        float4 hr = make_float4(0.f, 0.f, 0.f, 0.f);
        if (rvalid) hr = ((const float4*)(h0 + (size_t)row * EMBED))[hl];
        acc.x = fmaf(rs, acc.x, hr.x);
        acc.y = fmaf(rs, acc.y, hr.y);
        acc.z = fmaf(rs, acc.z, hr.z);
        acc.w = fmaf(rs, acc.w, hr.w);

        if (half == 0) {
            if (rvalid) ((float4*)(out0 + (size_t)row * EMBED))[hl] = hr;
            float* dst = a_sh[wwarp + 8 * rr] + (hl >> 2) * 20 + (hl & 3) * 4;
            *(float4*)dst = acc;
        }
    }

    // ---- W slice into registers: thread (jj, q) holds W[j][16q..16q+15] ----
    int jj = lane >> 2;
    int q  = lane & 3;
    int j  = wwarp * 8 + jj;
    const float4* wrow = (const float4*)(W + j * EMBED + q * 16);
    float4 w0 = wrow[0], w1 = wrow[1], w2 = wrow[2], w3 = wrow[3];
    float  bj = b[j];

    __syncthreads();

    #pragma unroll
    for (int r = 0; r < 16; ++r) {
        const float* aq = a_sh[r] + q * 20;
        float4 a0 = ((const float4*)aq)[0];
        float4 a1 = ((const float4*)aq)[1];
        float4 a2 = ((const float4*)aq)[2];
        float4 a3 = ((const float4*)aq)[3];
        float p = a0.x*w0.x + a0.y*w0.y + a0.z*w0.z + a0.w*w0.w;
        p = fmaf(a1.x, w1.x, p); p = fmaf(a1.y, w1.y, p);
        p = fmaf(a1.z, w1.z, p); p = fmaf(a1.w, w1.w, p);
        p = fmaf(a2.x, w2.x, p); p = fmaf(a2.y, w2.y, p);
        p = fmaf(a2.z, w2.z, p); p = fmaf(a2.w, w2.w, p);
        p = fmaf(a3.x, w3.x, p); p = fmaf(a3.y, w3.y, p);
        p = fmaf(a3.z, w3.z, p); p = fmaf(a3.w, w3.w, p);
        p += __shfl_xor_sync(FULL, p, 1);
        p += __shfl_xor_sync(FULL, p, 2);
        if (q == 0) o_sh[r][j] = fmaxf(p + bj, 0.f);
    }
    __syncthreads();

    #pragma unroll
    for (int rr = 0; rr < 2; ++rr) {
        int r   = wwarp + 8 * rr;
        int row = rowbase + r;
        if (row < n) {
            float o1 = o_sh[r][lane];
            float o2 = o_sh[r][lane + 32];
            float sq = o1 * o1 + o2 * o2;
            #pragma unroll
            for (int o = 16; o; o >>= 1) sq += __shfl_xor_sync(FULL, sq, o);
            float inv = rsqrtf(fmaxf(sq, EPS_F * EPS_F));
            float* orow = out + (size_t)row * EMBED;
            orow[lane]      = o1 * inv;
            orow[lane + 32] = o2 * inv;
        }
    }
}

// ---------------------------------------------------------------------------
// K3: layer-2 propagation (reads g_ew / g_rs), 16 ROWS PER BLOCK (2 per warp),
// gather x4 unroll (8 edges/iter, 8 independent LDG.128s in flight).
// ---------------------------------------------------------------------------
__global__ void __launch_bounds__(256)
k_prop(const float* __restrict__ h_prev,
       const int*   __restrict__ ecol,
       const float* __restrict__ W,      // [64,64] row-major
       const float* __restrict__ b,
       float*       __restrict__ out, int n) {
    __shared__ float a_sh[16][80];
    __shared__ float o_sh[16][66];

    int wwarp = threadIdx.x >> 5;
    int lane  = threadIdx.x & 31;
    int rowbase = blockIdx.x * 16;

    int half = lane >> 4;
    int hl   = lane & 15;

    #pragma unroll
    for (int rr = 0; rr < 2; ++rr) {
        int row = rowbase + wwarp + 8 * rr;
        bool rvalid = row < n;

        int beg = 0, end = 0;
        if (rvalid) { beg = g_rowptr[row]; end = g_rowptr[row + 1]; }

        float4 acc0 = make_float4(0.f, 0.f, 0.f, 0.f);
        float4 acc1 = make_float4(0.f, 0.f, 0.f, 0.f);
        for (int base = beg; base < end; base += 32) {
            int   idx = base + lane;
            bool  v   = idx < end;
            int   c   = v ? ecol[idx] : 0;
            float w   = v ? g_ew[idx] : 0.f;
            int   cnt = min(32, end - base);
            int j = 0;
            for (; j + 8 <= cnt; j += 8) {
                int   cc0 = __shfl_sync(FULL, c, j + half);
                int   cc1 = __shfl_sync(FULL, c, j + 2 + half);
                int   cc2 = __shfl_sync(FULL, c, j + 4 + half);
                int   cc3 = __shfl_sync(FULL, c, j + 6 + half);
                float ws0 = __shfl_sync(FULL, w, j + half);
                float ws1 = __shfl_sync(FULL, w, j + 2 + half);
                float ws2 = __shfl_sync(FULL, w, j + 4 + half);
                float ws3 = __shfl_sync(FULL, w, j + 6 + half);
                float4 hv0 = ((const float4*)(h_prev + (size_t)cc0 * EMBED))[hl];
                float4 hv1 = ((const float4*)(h_prev + (size_t)cc1 * EMBED))[hl];
                float4 hv2 = ((const float4*)(h_prev + (size_t)cc2 * EMBED))[hl];
                float4 hv3 = ((const float4*)(h_prev + (size_t)cc3 * EMBED))[hl];
                acc0.x = fmaf(ws0, hv0.x, acc0.x); acc0.y = fmaf(ws0, hv0.y, acc0.y);
                acc0.z = fmaf(ws0, hv0.z, acc0.z); acc0.w = fmaf(ws0, hv0.w, acc0.w);
                acc1.x = fmaf(ws1, hv1.x, acc1.x); acc1.y = fmaf(ws1, hv1.y, acc1.y);
                acc1.z = fmaf(ws1, hv1.z, acc1.z); acc1.w = fmaf(ws1, hv1.w, acc1.w);
                acc0.x = fmaf(ws2, hv2.x, acc0.x); acc0.y = fmaf(ws2, hv2.y, acc0.y);
                acc0.z = fmaf(ws2, hv2.z, acc0.z); acc0.w = fmaf(ws2, hv2.w, acc0.w);
                acc1.x = fmaf(ws3, hv3.x, acc1.x); acc1.y = fmaf(ws3, hv3.y, acc1.y);
                acc1.z = fmaf(ws3, hv3.z, acc1.z); acc1.w = fmaf(ws3, hv3.w, acc1.w);
            }
            for (; j < cnt; j += 2) {
                int   jj = j + half; if (jj >= cnt) jj = cnt - 1;
                int   cc = __shfl_sync(FULL, c, jj);
                float ws = __shfl_sync(FULL, w, jj);
                if (half && (j + 1 >= cnt)) ws = 0.f;
                float4 hv = ((const float4*)(h_prev + (size_t)cc * EMBED))[hl];
                acc0.x = fmaf(ws, hv.x, acc0.x); acc0.y = fmaf(ws, hv.y, acc0.y);
                acc0.z = fmaf(ws, hv.z, acc0.z); acc0.w = fmaf(ws, hv.w, acc0.w);
            }
        }
        float4 acc = make_float4(acc0.x + acc1.x, acc0.y + acc1.y,
                                 acc0.z + acc1.z, acc0.w + acc1.w);
        acc.x += __shfl_xor_sync(FULL, acc.x, 16);
        acc.y += __shfl_xor_sync(FULL, acc.y, 16);
        acc.z += __shfl_xor_sync(FULL, acc.z, 16);
        acc.w += __shfl_xor_sync(FULL, acc.w, 16);

        float rs = (beg < end) ? g_rs[row] : 0.f;
        float4 hr = make_float4(0.f, 0.f, 0.f, 0.f);
        if (rvalid) hr = ((const float4*)(h_prev + (size_t)row * EMBED))[hl];
        acc.x = fmaf(rs, acc.x, hr.x);
        acc.y = fmaf(rs, acc.y, hr.y);
        acc.z = fmaf(rs, acc.z, hr.z);
        acc.w = fmaf(rs, acc.w, hr.w);

        if (half == 0) {
            float* dst = a_sh[wwarp + 8 * rr] + (hl >> 2) * 20 + (hl & 3) * 4;
            *(float4*)dst = acc;
        }
    }

    int jj = lane >> 2;
    int q  = lane & 3;
    int j  = wwarp * 8 + jj;
    const float4* wrow = (const float4*)(W + j * EMBED + q * 16);
    float4 w0 = wrow[0], w1 = wrow[1], w2 = wrow[2], w3 = wrow[3];
    float  bj = b[j];

    __syncthreads();

    #pragma unroll
    for (int r = 0; r < 16; ++r) {
        const float* aq = a_sh[r] + q * 20;
        float4 a0 = ((const float4*)aq)[0];
        float4 a1 = ((const float4*)aq)[1];
        float4 a2 = ((const float4*)aq)[2];
        float4 a3 = ((const float4*)aq)[3];
        float p = a0.x*w0.x + a0.y*w0.y + a0.z*w0.z + a0.w*w0.w;
        p = fmaf(a1.x, w1.x, p); p = fmaf(a1.y, w1.y, p);
        p = fmaf(a1.z, w1.z, p); p = fmaf(a1.w, w1.w, p);
        p = fmaf(a2.x, w2.x, p); p = fmaf(a2.y, w2.y, p);
        p = fmaf(a2.z, w2.z, p); p = fmaf(a2.w, w2.w, p);
        p = fmaf(a3.x, w3.x, p); p = fmaf(a3.y, w3.y, p);
        p = fmaf(a3.z, w3.z, p); p = fmaf(a3.w, w3.w, p);
        p += __shfl_xor_sync(FULL, p, 1);
        p += __shfl_xor_sync(FULL, p, 2);
        if (q == 0) o_sh[r][j] = fmaxf(p + bj, 0.f);
    }
    __syncthreads();

    #pragma unroll
    for (int rr = 0; rr < 2; ++rr) {
        int r   = wwarp + 8 * rr;
        int row = rowbase + r;
        if (row < n) {
            float o1 = o_sh[r][lane];
            float o2 = o_sh[r][lane + 32];
            float sq = o1 * o1 + o2 * o2;
            #pragma unroll
            for (int o = 16; o; o >>= 1) sq += __shfl_xor_sync(FULL, sq, o);
            float inv = rsqrtf(fmaxf(sq, EPS_F * EPS_F));
            float* orow = out + (size_t)row * EMBED;
            orow[lane]      = o1 * inv;
            orow[lane + 32] = o2 * inv;
        }
    }
}

// ---------------------------------------------------------------------------
extern "C" void kernel_launch(void* const* d_in, const int* in_sizes, int n_in,
                              void* d_out, int out_size) {
    const float* h0    = (const float*)d_in[0];
    const float* h_att = (const float*)d_in[1];
    const float* t_att = (const float*)d_in[2];
    const float* w1    = (const float*)d_in[3];
    const float* b1    = (const float*)d_in[4];
    const float* w2    = (const float*)d_in[5];
    const float* b2    = (const float*)d_in[6];
    const int*   erow  = (const int*)d_in[7];
    const int*   ecol  = (const int*)d_in[8];
    float* out = (float*)d_out;

    int n = in_sizes[0] / EMBED;
    int e = in_sizes[8];
    if (n > MAX_NODES) n = MAX_NODES;
    if (e > MAX_EDGES) e = MAX_EDGES;

    {   // row pointers: int4 boundary scan over sorted erow
        int threads = 256;
        int quads   = (e + 3) / 4;
        int blocks  = (quads + threads - 1) / threads;
        k_rowptr<<<blocks, threads>>>(erow, n, e);
    }
    {
        int blocks = (n + 15) / 16;        // 16 rows per block, 2 per warp
        float* l1 = out + (size_t)n * EMBED;
        float* l2 = out + (size_t)2 * n * EMBED;
        // layer 1: fused softmax + propagation; also emits layer-0 copy
        k_prop1_fused<<<blocks, 256>>>(h0, h_att, t_att, ecol, w1, b1, out, l1, n);
        // layer 2: standard propagation using cached weights
        k_prop<<<blocks, 256>>>(l1, ecol, w2, b2, l2, n);
    }
}